// round 3
// baseline (speedup 1.0000x reference)
#include <cuda_runtime.h>
#include <math.h>

#define C_CLASSES 10000
#define K_PROTO   4
#define D_DIM     2048
#define N_PROTO   (C_CLASSES * K_PROTO)   // 40000
#define WARPS_PER_BLOCK 8
#define BLOCK1 (WARPS_PER_BLOCK * 32)     // 256
#define GRID1 (N_PROTO / WARPS_PER_BLOCK) // 5000

// scratch (no cudaMalloc allowed). g_pmin/g_psum/g_lbl are fully overwritten
// before being read on every run; g_ticket is reset by the last block so each
// graph replay starts from identical state.
__device__ float g_pmin[GRID1];
__device__ float g_psum[GRID1];
__device__ float g_lbl[K_PROTO];
__device__ unsigned int g_ticket = 0;

__global__ __launch_bounds__(BLOCK1) void fused_kernel(
    const float* __restrict__ proto, const float* __restrict__ feat,
    const int* __restrict__ label, float* __restrict__ out) {
    __shared__ float4 sf[D_DIM / 4];   // 8 KB feature tile
    __shared__ float  wdist[WARPS_PER_BLOCK];
    __shared__ bool   amLast;

    const int tid  = threadIdx.x;
    const int lane = tid & 31;
    const int warp = tid >> 5;
    const int lbl  = *label;

    const float4* __restrict__ f4 = reinterpret_cast<const float4*>(feat);
    for (int i = tid; i < D_DIM / 4; i += BLOCK1) sf[i] = f4[i];
    __syncthreads();

    // ---- distance: one warp per prototype ----
    const int p = blockIdx.x * WARPS_PER_BLOCK + warp;
    const float4* __restrict__ pp =
        reinterpret_cast<const float4*>(proto + (size_t)p * D_DIM);
    float acc = 0.0f;
#pragma unroll
    for (int i = 0; i < 16; ++i) {       // 16 float4 per lane = 2048/(32*4)
        float4 v = __ldcs(pp + lane + i * 32);   // streaming: read-once data
        float4 f = sf[lane + i * 32];
        float dx = v.x - f.x;
        float dy = v.y - f.y;
        float dz = v.z - f.z;
        float dw = v.w - f.w;
        acc += dx * dx + dy * dy + dz * dz + dw * dw;
    }
#pragma unroll
    for (int o = 16; o > 0; o >>= 1)
        acc += __shfl_xor_sync(0xFFFFFFFFu, acc, o);

    if (lane == 0) {
        wdist[warp] = acc;
        if ((p >> 2) == lbl) g_lbl[p & 3] = acc;   // label's raw distances
    }
    __syncthreads();

    // ---- block partial: (m, s) with s = sum_w exp(m - d_w) ----
    if (tid == 0) {
        float m = wdist[0];
#pragma unroll
        for (int w = 1; w < WARPS_PER_BLOCK; ++w) m = fminf(m, wdist[w]);
        float s = 0.0f;
#pragma unroll
        for (int w = 0; w < WARPS_PER_BLOCK; ++w) s += expf(m - wdist[w]);
        g_pmin[blockIdx.x] = m;
        g_psum[blockIdx.x] = s;
        __threadfence();
        unsigned int t = atomicAdd(&g_ticket, 1u);
        amLast = (t == GRID1 - 1);
    }
    __syncthreads();
    if (!amLast) return;

    // ---- last block: merge 5000 partials (fixed order -> deterministic) ----
    __shared__ float rm[BLOCK1], rs[BLOCK1];
    float m = INFINITY, s = 0.0f;
    for (int i = tid; i < GRID1; i += BLOCK1) {
        float pm = g_pmin[i], ps = g_psum[i];
        float nm = fminf(m, pm);
        s = s * expf(nm - m) + ps * expf(nm - pm);
        m = nm;
    }
    rm[tid] = m; rs[tid] = s;
    __syncthreads();
#pragma unroll
    for (int step = BLOCK1 / 2; step > 0; step >>= 1) {
        if (tid < step) {
            float m1 = rm[tid], s1 = rs[tid];
            float m2 = rm[tid + step], s2 = rs[tid + step];
            float nm = fminf(m1, m2);
            rm[tid] = nm;
            rs[tid] = s1 * expf(nm - m1) + s2 * expf(nm - m2);
        }
        __syncthreads();
    }

    if (tid == 0) {
        const float log_one = -rm[0] + logf(rs[0]);
        float prob = 0.0f;
#pragma unroll
        for (int k = 0; k < K_PROTO; ++k)
            prob += log_one + g_lbl[k];    // log_one - logits
        out[0] = prob;
        g_ticket = 0;                       // reset for next graph replay
        __threadfence();
    }
}

extern "C" void kernel_launch(void* const* d_in, const int* in_sizes, int n_in,
                              void* d_out, int out_size) {
    const float* feature = (const float*)d_in[0];
    const int*   label   = (const int*)d_in[1];
    const float* protos  = (const float*)d_in[2];
    float* out = (float*)d_out;

    fused_kernel<<<GRID1, BLOCK1>>>(protos, feature, label, out);
}

// round 4
// speedup vs baseline: 1.1507x; 1.1507x over previous
#include <cuda_runtime.h>
#include <math.h>

#define C_CLASSES 10000
#define K_PROTO   4
#define D_DIM     2048
#define N_PROTO   (C_CLASSES * K_PROTO)   // 40000
#define WARPS_PER_BLOCK 8
#define BLOCK1 (WARPS_PER_BLOCK * 32)     // 256
#define GRID1 (N_PROTO / WARPS_PER_BLOCK) // 5000
#define BLOCK2 1024

// scratch (no cudaMalloc allowed). All fully overwritten each run before being
// read by kernel 2 — no reset needed, graph-replay deterministic.
__device__ float g_pmin[GRID1];
__device__ float g_psum[GRID1];
__device__ float g_lbl[K_PROTO];

// Kernel 1: one warp per prototype distance; block emits one online-logsumexp
// partial (m, s) with plain stores. No fences, no atomics — nothing to disturb
// the HBM stream.
__global__ __launch_bounds__(BLOCK1) void dist_kernel(
    const float* __restrict__ proto, const float* __restrict__ feat,
    const int* __restrict__ label) {
    __shared__ float4 sf[D_DIM / 4];   // 8 KB feature tile
    __shared__ float  wdist[WARPS_PER_BLOCK];

    const int tid  = threadIdx.x;
    const int lane = tid & 31;
    const int warp = tid >> 5;

    const float4* __restrict__ f4 = reinterpret_cast<const float4*>(feat);
    for (int i = tid; i < D_DIM / 4; i += BLOCK1) sf[i] = f4[i];
    __syncthreads();

    const int p = blockIdx.x * WARPS_PER_BLOCK + warp;
    const float4* __restrict__ pp =
        reinterpret_cast<const float4*>(proto + (size_t)p * D_DIM);
    float acc = 0.0f;
#pragma unroll
    for (int i = 0; i < 16; ++i) {       // 16 float4 per lane = 2048/(32*4)
        float4 v = __ldcs(pp + lane + i * 32);   // streaming: read-once data
        float4 f = sf[lane + i * 32];
        float dx = v.x - f.x;
        float dy = v.y - f.y;
        float dz = v.z - f.z;
        float dw = v.w - f.w;
        acc += dx * dx + dy * dy + dz * dz + dw * dw;
    }
#pragma unroll
    for (int o = 16; o > 0; o >>= 1)
        acc += __shfl_xor_sync(0xFFFFFFFFu, acc, o);

    if (lane == 0) {
        wdist[warp] = acc;
        if ((p >> 2) == *label) g_lbl[p & 3] = acc;   // label's raw distances
    }
    __syncthreads();

    // warp 0, lanes 0..7 cooperate on the block partial
    if (warp == 0) {
        float d = (lane < WARPS_PER_BLOCK) ? wdist[lane] : INFINITY;
        float m = d;
#pragma unroll
        for (int o = 4; o > 0; o >>= 1)
            m = fminf(m, __shfl_xor_sync(0xFFu, m, o, 8));
        float e = (lane < WARPS_PER_BLOCK) ? expf(m - d) : 0.0f;
#pragma unroll
        for (int o = 4; o > 0; o >>= 1)
            e += __shfl_xor_sync(0xFFu, e, o, 8);
        if (lane == 0) {
            g_pmin[blockIdx.x] = m;
            g_psum[blockIdx.x] = e;
        }
    }
}

// Kernel 2: single block merges 5000 (m, s) partials — 40 KB, L2-hot.
__global__ __launch_bounds__(BLOCK2) void merge_kernel(
    float* __restrict__ out) {
    __shared__ float rm[BLOCK2], rs[BLOCK2];
    const int tid = threadIdx.x;

    float m = INFINITY, s = 0.0f;
    for (int i = tid; i < GRID1; i += BLOCK2) {
        float pm = g_pmin[i], ps = g_psum[i];
        float nm = fminf(m, pm);
        s = s * expf(nm - m) + ps * expf(nm - pm);
        m = nm;
    }
    rm[tid] = m; rs[tid] = s;
    __syncthreads();
#pragma unroll
    for (int step = BLOCK2 / 2; step > 0; step >>= 1) {
        if (tid < step) {
            float m1 = rm[tid], s1 = rs[tid];
            float m2 = rm[tid + step], s2 = rs[tid + step];
            float nm = fminf(m1, m2);
            rm[tid] = nm;
            rs[tid] = s1 * expf(nm - m1) + s2 * expf(nm - m2);
        }
        __syncthreads();
    }

    if (tid == 0) {
        const float log_one = -rm[0] + logf(rs[0]);
        float prob = 0.0f;
#pragma unroll
        for (int k = 0; k < K_PROTO; ++k)
            prob += log_one + g_lbl[k];    // log_one - logits
        out[0] = prob;
    }
}

extern "C" void kernel_launch(void* const* d_in, const int* in_sizes, int n_in,
                              void* d_out, int out_size) {
    const float* feature = (const float*)d_in[0];
    const int*   label   = (const int*)d_in[1];
    const float* protos  = (const float*)d_in[2];
    float* out = (float*)d_out;

    dist_kernel<<<GRID1, BLOCK1>>>(protos, feature, label);
    merge_kernel<<<1, BLOCK2>>>(out);
}